// round 2
// baseline (speedup 1.0000x reference)
#include <cuda_runtime.h>
#include <cuda_bf16.h>
#include <mma.h>
#include <math.h>
using namespace nvcuda;

// ---------------- constants ----------------
#define T1024 1024
#define D 1024
#define H 16
#define HD 64
#define E 8
#define F 2560
#define QKVN 3072
#define FC_N (2*F)   // 5120

// ---------------- scratch (device globals; no allocation allowed) ----------------
__device__ float g_h1[T1024 * D];
__device__ float g_qkv[T1024 * QKVN];
__device__ float g_KT[H * HD * T1024];
__device__ float g_S[(long)H * T1024 * T1024];
__device__ float g_attn[T1024 * D];
__device__ float g_tmp[T1024 * D];
__device__ float g_xres[T1024 * D];
__device__ float g_h2[T1024 * D];
__device__ float g_xg[E * T1024 * D];
__device__ float g_h12[(long)E * T1024 * FC_N];
__device__ float g_act[(long)E * T1024 * F];
__device__ float g_y[(long)E * T1024 * D];
__device__ int   g_cnt[E];
__device__ float g_sums[E];
__device__ int   g_tok[E * T1024];
__device__ float g_gwf[T1024];

// ---------------- small kernels ----------------
__global__ void zero_k() {
    int i = threadIdx.x;
    if (i < E) { g_cnt[i] = 0; g_sums[i] = 0.f; }
}

__global__ void layernorm_k(const float* __restrict__ x, const float* __restrict__ w,
                            const float* __restrict__ b, float* __restrict__ y) {
    int t = blockIdx.x, tid = threadIdx.x;
    const float* xr = x + (long)t * D;
    float v[4], s = 0.f, ss = 0.f;
#pragma unroll
    for (int i = 0; i < 4; i++) {
        float a = xr[tid + i * 256];
        v[i] = a; s += a; ss += a * a;
    }
    __shared__ float r1[256], r2[256];
    r1[tid] = s; r2[tid] = ss; __syncthreads();
    for (int st = 128; st > 0; st >>= 1) {
        if (tid < st) { r1[tid] += r1[tid + st]; r2[tid] += r2[tid + st]; }
        __syncthreads();
    }
    float mean = r1[0] * (1.f / D);
    float var  = r2[0] * (1.f / D) - mean * mean;
    float inv  = rsqrtf(var + 1e-5f);
#pragma unroll
    for (int i = 0; i < 4; i++) {
        int d = tid + i * 256;
        y[(long)t * D + d] = (v[i] - mean) * inv * w[d] + b[d];
    }
}

// fused: xres = x + tmp + bias ; h2 = LN(xres)
__global__ void resln_k(const float* __restrict__ x, const float* __restrict__ tmp,
                        const float* __restrict__ bias,
                        const float* __restrict__ w, const float* __restrict__ b,
                        float* __restrict__ xres, float* __restrict__ h2) {
    int t = blockIdx.x, tid = threadIdx.x;
    float v[4], s = 0.f, ss = 0.f;
#pragma unroll
    for (int i = 0; i < 4; i++) {
        int d = tid + i * 256;
        float a = x[(long)t * D + d] + tmp[(long)t * D + d] + bias[d];
        v[i] = a; s += a; ss += a * a;
        xres[(long)t * D + d] = a;
    }
    __shared__ float r1[256], r2[256];
    r1[tid] = s; r2[tid] = ss; __syncthreads();
    for (int st = 128; st > 0; st >>= 1) {
        if (tid < st) { r1[tid] += r1[tid + st]; r2[tid] += r2[tid + st]; }
        __syncthreads();
    }
    float mean = r1[0] * (1.f / D);
    float var  = r2[0] * (1.f / D) - mean * mean;
    float inv  = rsqrtf(var + 1e-5f);
#pragma unroll
    for (int i = 0; i < 4; i++) {
        int d = tid + i * 256;
        h2[(long)t * D + d] = (v[i] - mean) * inv * w[d] + b[d];
    }
}

__global__ void qkvbias_k(const float* __restrict__ b) {
    int t = blockIdx.x, c = threadIdx.x * 4;
    float4 v = *(float4*)&g_qkv[(long)t * QKVN + c];
    float4 bb = *(const float4*)&b[c];
    v.x += bb.x; v.y += bb.y; v.z += bb.z; v.w += bb.w;
    *(float4*)&g_qkv[(long)t * QKVN + c] = v;
}

__global__ void rope_k() {
    int t = blockIdx.x, h = blockIdx.y, i = threadIdx.x; // 32 threads
    float inv = powf(10000.f, -(2.f * (float)i) / 64.f);
    float fr = (float)t * inv;
    float c = cosf(fr), s = sinf(fr);
    float* q = g_qkv + (long)t * QKVN + h * HD;
    float q1 = q[i], q2 = q[i + 32];
    q[i]      = q1 * c - q2 * s;
    q[i + 32] = q1 * s + q2 * c;
    float* k = q + D;
    float k1 = k[i], k2 = k[i + 32];
    k[i]      = k1 * c - k2 * s;
    k[i + 32] = k1 * s + k2 * c;
}

__global__ void ktrans_k() {
    int gid = blockIdx.x * 256 + threadIdx.x; // H*HD*T = 1M
    int k = gid & 1023;
    int d = (gid >> 10) & 63;
    int h = gid >> 16;
    g_KT[gid] = g_qkv[(long)k * QKVN + D + h * HD + d];
}

__global__ void attn_softmax_k(const int* __restrict__ ids) {
    int q = blockIdx.x, h = blockIdx.y, tid = threadIdx.x;
    float* row = g_S + ((long)h * T1024 + q) * T1024;
    int id = ids[q];
    bool glob = (id >= 2 && id < 8);
    float vals[4];
    float mx = -3.4e38f;
#pragma unroll
    for (int i = 0; i < 4; i++) {
        int k = tid + i * 256;
        bool allowed = glob || (q >= k);
        float v = allowed ? row[k] * 0.125f : -3.402823466e38f;
        vals[i] = v;
        mx = fmaxf(mx, v);
    }
    __shared__ float red[256];
    red[tid] = mx; __syncthreads();
    for (int st = 128; st > 0; st >>= 1) {
        if (tid < st) red[tid] = fmaxf(red[tid], red[tid + st]);
        __syncthreads();
    }
    float M = red[0]; __syncthreads();
    float s = 0.f;
#pragma unroll
    for (int i = 0; i < 4; i++) {
        float e = __expf(vals[i] - M);
        vals[i] = e; s += e;
    }
    red[tid] = s; __syncthreads();
    for (int st = 128; st > 0; st >>= 1) {
        if (tid < st) red[tid] += red[tid + st];
        __syncthreads();
    }
    float z = 1.f / red[0];
#pragma unroll
    for (int i = 0; i < 4; i++) row[tid + i * 256] = vals[i] * z;
}

// ---------------- TF32 tensor-core GEMM ----------------
// C[z] = A[z] @ B[z]; full tiles (M,N,K multiples of tile); optional per-z row
// count guard (cntPtr) for MoE — blocks beyond the padded count exit.
template<int BM, int BN, int BK, int WM, int WN>
__global__ void __launch_bounds__(256, 2)
gemm_tf32(const float* __restrict__ A, int lda, long sA,
          const float* __restrict__ B, int ldb, long sB,
          float* __restrict__ C, int ldc, long sC,
          int K, const int* __restrict__ cntPtr) {
    int z = blockIdx.z;
    int m0 = blockIdx.y * BM;
    if (cntPtr && m0 >= cntPtr[z]) return;
    int n0 = blockIdx.x * BN;
    A += (long)z * sA; B += (long)z * sB; C += (long)z * sC;

    constexpr int AP = BK + 4;
    constexpr int BP = BN + 4;
    __shared__ __align__(16) float As[BM][AP];
    __shared__ __align__(16) float Bs[BK][BP];

    constexpr int WARPS_M = BM / WM;
    constexpr int WARPS_N = BN / WN;
    constexpr int NT = WARPS_M * WARPS_N * 32;
    constexpr int MI = WM / 16, NI = WN / 16;

    int tid = threadIdx.x;
    int w = tid >> 5;
    int wm = w % WARPS_M, wn = w / WARPS_M;
    int mw0 = wm * WM, nw0 = wn * WN;

    wmma::fragment<wmma::accumulator, 16, 16, 8, float> acc[MI][NI];
#pragma unroll
    for (int i = 0; i < MI; i++)
#pragma unroll
        for (int j = 0; j < NI; j++) wmma::fill_fragment(acc[i][j], 0.f);

    for (int k0 = 0; k0 < K; k0 += BK) {
#pragma unroll
        for (int i = tid; i < BM * (BK / 4); i += NT) {
            int m = i / (BK / 4), kq = (i % (BK / 4)) * 4;
            *(float4*)&As[m][kq] = *(const float4*)&A[(long)(m0 + m) * lda + k0 + kq];
        }
#pragma unroll
        for (int i = tid; i < BK * (BN / 4); i += NT) {
            int kk = i / (BN / 4), nq = (i % (BN / 4)) * 4;
            *(float4*)&Bs[kk][nq] = *(const float4*)&B[(long)(k0 + kk) * ldb + n0 + nq];
        }
        __syncthreads();
#pragma unroll
        for (int k8 = 0; k8 < BK; k8 += 8) {
            wmma::fragment<wmma::matrix_a, 16, 16, 8, wmma::precision::tf32, wmma::row_major> af[MI];
            wmma::fragment<wmma::matrix_b, 16, 16, 8, wmma::precision::tf32, wmma::row_major> bf[NI];
#pragma unroll
            for (int i = 0; i < MI; i++) {
                wmma::load_matrix_sync(af[i], &As[mw0 + i * 16][k8], AP);
#pragma unroll
                for (int t = 0; t < af[i].num_elements; t++)
                    af[i].x[t] = wmma::__float_to_tf32(af[i].x[t]);
            }
#pragma unroll
            for (int j = 0; j < NI; j++) {
                wmma::load_matrix_sync(bf[j], &Bs[k8][nw0 + j * 16], BP);
#pragma unroll
                for (int t = 0; t < bf[j].num_elements; t++)
                    bf[j].x[t] = wmma::__float_to_tf32(bf[j].x[t]);
            }
#pragma unroll
            for (int i = 0; i < MI; i++)
#pragma unroll
                for (int j = 0; j < NI; j++)
                    wmma::mma_sync(acc[i][j], af[i], bf[j], acc[i][j]);
        }
        __syncthreads();
    }
#pragma unroll
    for (int i = 0; i < MI; i++)
#pragma unroll
        for (int j = 0; j < NI; j++)
            wmma::store_matrix_sync(&C[(long)(m0 + mw0 + i * 16) * ldc + n0 + nw0 + j * 16],
                                    acc[i][j], ldc, wmma::mem_row_major);
}

// ---------------- gate + routing + gather ----------------
__global__ void gate_route_k(const float* __restrict__ gw_mat, const float* __restrict__ gb) {
    int t = blockIdx.x, tid = threadIdx.x;
    const float* xr = g_h2 + (long)t * D;
    float p[E];
#pragma unroll
    for (int e = 0; e < E; e++) p[e] = 0.f;
    for (int d = tid; d < D; d += 256) {
        float xv = xr[d];
#pragma unroll
        for (int e = 0; e < E; e++) p[e] += xv * gw_mat[d * E + e];
    }
    __shared__ float red[256];
    __shared__ float logits[E];
    for (int e = 0; e < E; e++) {
        red[tid] = p[e]; __syncthreads();
        for (int st = 128; st > 0; st >>= 1) {
            if (tid < st) red[tid] += red[tid + st];
            __syncthreads();
        }
        if (tid == 0) logits[e] = red[0] + gb[e];
        __syncthreads();
    }
    __shared__ int sh_slot, sh_e;
    if (tid == 0) {
        float mx = -3.4e38f;
        for (int e = 0; e < E; e++) mx = fmaxf(mx, logits[e]);
        float Z = 0.f, pr[E];
        for (int e = 0; e < E; e++) { pr[e] = expf(logits[e] - mx); Z += pr[e]; }
        float best = -1.f; int bi = 0;
        for (int e = 0; e < E; e++) {
            float v = pr[e] / Z;
            if (v > best) { best = v; bi = e; }
        }
        int slot = atomicAdd(&g_cnt[bi], 1);
        atomicAdd(&g_sums[bi], best);
        g_tok[bi * T1024 + slot] = t;
        g_gwf[t] = best;
        sh_slot = slot; sh_e = bi;
    }
    __syncthreads();
    float* dst = g_xg + ((long)sh_e * T1024 + sh_slot) * D;
    for (int d = tid; d < D; d += 256) dst[d] = xr[d];
}

// zero-pad gathered rows up to multiple of 128 so wmma full-tile loads are clean
__global__ void pad_k() {
    int e = blockIdx.x;
    int cnt = g_cnt[e];
    int cp = (cnt + 127) & ~127;
    int row = cnt + blockIdx.y;
    if (row >= cp) return;
    float* dst = g_xg + ((long)e * T1024 + row) * D;
    for (int d = threadIdx.x; d < D; d += 256) dst[d] = 0.f;
}

// GLU activation with fused fc bias (exact gelu)
__global__ void moe_act_k(const float* __restrict__ fcb) {
    int e = blockIdx.z;
    int m = blockIdx.y;
    int cp = (g_cnt[e] + 127) & ~127;
    if (m >= cp) return;
    int f = blockIdx.x * 256 + threadIdx.x; // F = 2560, grid.x = 10
    const float* row = g_h12 + ((long)e * T1024 + m) * FC_N;
    const float* b = fcb + (long)e * FC_N;
    float x1 = row[f] + b[f];
    float x2 = row[F + f] + b[F + f];
    float g = 0.5f * x2 * (1.f + erff(x2 * 0.70710678118654752f));
    g_act[((long)e * T1024 + m) * F + f] = x1 * g;
}

// scatter epilogue: out[t] = xres[t] + (y[m] + eout_b) * gw[t]
__global__ void scatter_k(const float* __restrict__ eob, float* __restrict__ out) {
    int e = blockIdx.x, m = blockIdx.y;
    if (m >= g_cnt[e]) return;
    int t = g_tok[e * T1024 + m];
    float g = g_gwf[t];
    const float* y = g_y + ((long)e * T1024 + m) * D;
    const float* bias = eob + (long)e * D;
    for (int d = threadIdx.x; d < D; d += 256)
        out[(long)t * D + d] = g_xres[(long)t * D + d] + (y[d] + bias[d]) * g;
}

__global__ void moe_loss_k(float* __restrict__ out_loss) {
    if (threadIdx.x == 0) {
        float l = 0.f;
        for (int e = 0; e < E; e++) {
            float u = g_sums[e] / ((float)g_cnt[e] + 1e-8f);
            float d = u - 1.f / (float)E;
            l += d * d;
        }
        out_loss[0] = l;
    }
}

// ---------------- host ----------------
static float* sym_addr(const void* sym) {
    void* p = nullptr;
    cudaGetSymbolAddress(&p, sym);
    return (float*)p;
}

extern "C" void kernel_launch(void* const* d_in, const int* in_sizes, int n_in,
                              void* d_out, int out_size) {
    const float* x      = (const float*)d_in[0];
    const int*   ids    = (const int*)d_in[1];
    const float* ln1w   = (const float*)d_in[2];
    const float* ln1b   = (const float*)d_in[3];
    const float* qkvw   = (const float*)d_in[4];
    const float* qkvb   = (const float*)d_in[5];
    const float* aow    = (const float*)d_in[6];
    const float* aob    = (const float*)d_in[7];
    const float* ln2w   = (const float*)d_in[8];
    const float* ln2b   = (const float*)d_in[9];
    const float* gatew  = (const float*)d_in[10];
    const float* gateb  = (const float*)d_in[11];
    const float* fcw    = (const float*)d_in[12];
    const float* fcb    = (const float*)d_in[13];
    const float* eow    = (const float*)d_in[14];
    const float* eob    = (const float*)d_in[15];
    float* out = (float*)d_out;

    float* p_h1   = sym_addr(g_h1);
    float* p_qkv  = sym_addr(g_qkv);
    float* p_KT   = sym_addr(g_KT);
    float* p_S    = sym_addr(g_S);
    float* p_attn = sym_addr(g_attn);
    float* p_tmp  = sym_addr(g_tmp);
    float* p_xres = sym_addr(g_xres);
    float* p_h2   = sym_addr(g_h2);
    float* p_xg   = sym_addr(g_xg);
    float* p_h12  = sym_addr(g_h12);
    float* p_act  = sym_addr(g_act);
    float* p_y    = sym_addr(g_y);
    int*   p_cnt  = (int*)sym_addr(g_cnt);

    zero_k<<<1, 32>>>();
    layernorm_k<<<T1024, 256>>>(x, ln1w, ln1b, p_h1);

    // qkv = h1 @ qkv_w   [1024,1024]x[1024,3072]
    gemm_tf32<128,128,32,64,32><<<dim3(QKVN/128, T1024/128, 1), 256>>>(
        p_h1, D, 0, qkvw, QKVN, 0, p_qkv, QKVN, 0, D, nullptr);
    qkvbias_k<<<T1024, 768>>>(qkvb);
    rope_k<<<dim3(T1024, H), 32>>>();
    ktrans_k<<<(H * HD * T1024) / 256, 256>>>();

    // S[h] = Q[h] @ K[h]^T : [1024,64]x[64,1024] per head
    gemm_tf32<128,128,32,64,32><<<dim3(T1024/128, T1024/128, H), 256>>>(
        p_qkv, QKVN, 64, p_KT, T1024, (long)HD * T1024,
        p_S, T1024, (long)T1024 * T1024, HD, nullptr);

    attn_softmax_k<<<dim3(T1024, H), 256>>>(ids);

    // attn[h] = P[h] @ V[h] : [1024,1024]x[1024,64] per head
    gemm_tf32<128,64,32,64,16><<<dim3(1, T1024/128, H), 256>>>(
        p_S, T1024, (long)T1024 * T1024, p_qkv + 2 * D, QKVN, 64,
        p_attn, D, 64, T1024, nullptr);

    // tmp = attn @ Wo
    gemm_tf32<128,128,32,64,32><<<dim3(D/128, T1024/128, 1), 256>>>(
        p_attn, D, 0, aow, D, 0, p_tmp, D, 0, D, nullptr);

    // xres = x + tmp + bo ; h2 = LN2(xres)
    resln_k<<<T1024, 256>>>(x, p_tmp, aob, ln2w, ln2b, p_xres, p_h2);

    gate_route_k<<<T1024, 256>>>(gatew, gateb);
    pad_k<<<dim3(E, 127), 256>>>();

    // h12 = xg @ fc_w  per expert (guarded by cnt)
    gemm_tf32<128,128,32,64,32><<<dim3(FC_N/128, T1024/128, E), 256>>>(
        p_xg, D, (long)T1024 * D, fcw, FC_N, (long)D * FC_N,
        p_h12, FC_N, (long)T1024 * FC_N, D, p_cnt);

    moe_act_k<<<dim3(F/256, T1024, E), 256>>>(fcb);

    // y = act @ eout_w per expert (guarded)
    gemm_tf32<128,128,32,64,32><<<dim3(D/128, T1024/128, E), 256>>>(
        p_act, F, (long)T1024 * F, eow, D, (long)F * D,
        p_y, D, (long)T1024 * D, F, p_cnt);

    scatter_k<<<dim3(E, T1024), 256>>>(eob, out);

    if (out_size > T1024 * D)
        moe_loss_k<<<1, 32>>>(out + (long)T1024 * D);
}

// round 3
// speedup vs baseline: 3.0143x; 3.0143x over previous
#include <cuda_runtime.h>
#include <cuda_bf16.h>
#include <mma.h>
#include <math.h>
using namespace nvcuda;

// ---------------- constants ----------------
#define T1024 1024
#define D 1024
#define H 16
#define HD 64
#define E 8
#define F 2560
#define QKVN 3072
#define FC_N (2*F)   // 5120

// ---------------- scratch (device globals; no allocation allowed) ----------------
__device__ float g_h1[T1024 * D];
__device__ float g_qkv[T1024 * QKVN];
__device__ float g_KT[H * HD * T1024];
__device__ float g_S[(long)H * T1024 * T1024];
__device__ float g_attn[T1024 * D];
__device__ float g_tmp[T1024 * D];
__device__ float g_xres[T1024 * D];
__device__ float g_h2[T1024 * D];
__device__ float g_xg[E * T1024 * D];
__device__ float g_h12[(long)E * T1024 * FC_N];
__device__ float g_act[(long)E * T1024 * F];
__device__ float g_y[(long)E * T1024 * D];
__device__ int   g_cnt[E];
__device__ float g_sums[E];
__device__ int   g_tok[E * T1024];
__device__ float g_gwf[T1024];

// ---------------- small kernels ----------------
__global__ void zero_k() {
    int i = threadIdx.x;
    if (i < E) { g_cnt[i] = 0; g_sums[i] = 0.f; }
}

__global__ void layernorm_k(const float* __restrict__ x, const float* __restrict__ w,
                            const float* __restrict__ b, float* __restrict__ y) {
    int t = blockIdx.x, tid = threadIdx.x;
    const float* xr = x + (long)t * D;
    float v[4], s = 0.f, ss = 0.f;
#pragma unroll
    for (int i = 0; i < 4; i++) {
        float a = xr[tid + i * 256];
        v[i] = a; s += a; ss += a * a;
    }
    __shared__ float r1[256], r2[256];
    r1[tid] = s; r2[tid] = ss; __syncthreads();
    for (int st = 128; st > 0; st >>= 1) {
        if (tid < st) { r1[tid] += r1[tid + st]; r2[tid] += r2[tid + st]; }
        __syncthreads();
    }
    float mean = r1[0] * (1.f / D);
    float var  = r2[0] * (1.f / D) - mean * mean;
    float inv  = rsqrtf(var + 1e-5f);
#pragma unroll
    for (int i = 0; i < 4; i++) {
        int d = tid + i * 256;
        y[(long)t * D + d] = (v[i] - mean) * inv * w[d] + b[d];
    }
}

// fused: xres = x + tmp + bias ; h2 = LN(xres)
__global__ void resln_k(const float* __restrict__ x, const float* __restrict__ tmp,
                        const float* __restrict__ bias,
                        const float* __restrict__ w, const float* __restrict__ b,
                        float* __restrict__ xres, float* __restrict__ h2) {
    int t = blockIdx.x, tid = threadIdx.x;
    float v[4], s = 0.f, ss = 0.f;
#pragma unroll
    for (int i = 0; i < 4; i++) {
        int d = tid + i * 256;
        float a = x[(long)t * D + d] + tmp[(long)t * D + d] + bias[d];
        v[i] = a; s += a; ss += a * a;
        xres[(long)t * D + d] = a;
    }
    __shared__ float r1[256], r2[256];
    r1[tid] = s; r2[tid] = ss; __syncthreads();
    for (int st = 128; st > 0; st >>= 1) {
        if (tid < st) { r1[tid] += r1[tid + st]; r2[tid] += r2[tid + st]; }
        __syncthreads();
    }
    float mean = r1[0] * (1.f / D);
    float var  = r2[0] * (1.f / D) - mean * mean;
    float inv  = rsqrtf(var + 1e-5f);
#pragma unroll
    for (int i = 0; i < 4; i++) {
        int d = tid + i * 256;
        h2[(long)t * D + d] = (v[i] - mean) * inv * w[d] + b[d];
    }
}

__global__ void qkvbias_k(const float* __restrict__ b) {
    int t = blockIdx.x, c = threadIdx.x * 4;
    float4 v = *(float4*)&g_qkv[(long)t * QKVN + c];
    float4 bb = *(const float4*)&b[c];
    v.x += bb.x; v.y += bb.y; v.z += bb.z; v.w += bb.w;
    *(float4*)&g_qkv[(long)t * QKVN + c] = v;
}

__global__ void rope_k() {
    int t = blockIdx.x, h = blockIdx.y, i = threadIdx.x; // 32 threads
    float inv = powf(10000.f, -(2.f * (float)i) / 64.f);
    float fr = (float)t * inv;
    float c = cosf(fr), s = sinf(fr);
    float* q = g_qkv + (long)t * QKVN + h * HD;
    float q1 = q[i], q2 = q[i + 32];
    q[i]      = q1 * c - q2 * s;
    q[i + 32] = q1 * s + q2 * c;
    float* k = q + D;
    float k1 = k[i], k2 = k[i + 32];
    k[i]      = k1 * c - k2 * s;
    k[i + 32] = k1 * s + k2 * c;
}

__global__ void ktrans_k() {
    int gid = blockIdx.x * 256 + threadIdx.x; // H*HD*T = 1M
    int k = gid & 1023;
    int d = (gid >> 10) & 63;
    int h = gid >> 16;
    g_KT[gid] = g_qkv[(long)k * QKVN + D + h * HD + d];
}

__global__ void attn_softmax_k(const int* __restrict__ ids) {
    int q = blockIdx.x, h = blockIdx.y, tid = threadIdx.x;
    float* row = g_S + ((long)h * T1024 + q) * T1024;
    int id = ids[q];
    bool glob = (id >= 2 && id < 8);
    float vals[4];
    float mx = -3.4e38f;
#pragma unroll
    for (int i = 0; i < 4; i++) {
        int k = tid + i * 256;
        bool allowed = glob || (q >= k);
        float v = allowed ? row[k] * 0.125f : -3.402823466e38f;
        vals[i] = v;
        mx = fmaxf(mx, v);
    }
    __shared__ float red[256];
    red[tid] = mx; __syncthreads();
    for (int st = 128; st > 0; st >>= 1) {
        if (tid < st) red[tid] = fmaxf(red[tid], red[tid + st]);
        __syncthreads();
    }
    float M = red[0]; __syncthreads();
    float s = 0.f;
#pragma unroll
    for (int i = 0; i < 4; i++) {
        float e = __expf(vals[i] - M);
        vals[i] = e; s += e;
    }
    red[tid] = s; __syncthreads();
    for (int st = 128; st > 0; st >>= 1) {
        if (tid < st) red[tid] += red[tid + st];
        __syncthreads();
    }
    float z = 1.f / red[0];
#pragma unroll
    for (int i = 0; i < 4; i++) row[tid + i * 256] = vals[i] * z;
}

// ---------------- bf16 tensor-core GEMM (fp32 in/out, bf16 operands) ----------------
// C[z] = A[z] @ B[z]; M,N multiples of BM/BN (rows beyond may be garbage-padded
// scratch but within bounds); optional per-z row guard (cntPtr) for MoE.
template<int BM, int BN, int BK, int WM, int WN>
__global__ void __launch_bounds__(256, 2)
gemm_bf16(const float* __restrict__ A, int lda, long sA,
          const float* __restrict__ B, int ldb, long sB,
          float* __restrict__ C, int ldc, long sC,
          int K, const int* __restrict__ cntPtr) {
    int z = blockIdx.z;
    int m0 = blockIdx.y * BM;
    if (cntPtr && m0 >= cntPtr[z]) return;
    int n0 = blockIdx.x * BN;
    A += (long)z * sA; B += (long)z * sB; C += (long)z * sC;

    constexpr int AP = BK + 8;   // bf16 pad: 8 elems = 16 bytes
    constexpr int BP = BN + 8;
    __shared__ __align__(16) __nv_bfloat16 As[BM][AP];
    __shared__ __align__(16) __nv_bfloat16 Bs[BK][BP];

    constexpr int WARPS_M = BM / WM;
    constexpr int WARPS_N = BN / WN;
    constexpr int NT = WARPS_M * WARPS_N * 32;
    constexpr int MI = WM / 16, NI = WN / 16;

    int tid = threadIdx.x;
    int w = tid >> 5;
    int wm = w % WARPS_M, wn = w / WARPS_M;
    int mw0 = wm * WM, nw0 = wn * WN;

    wmma::fragment<wmma::accumulator, 16, 16, 16, float> acc[MI][NI];
#pragma unroll
    for (int i = 0; i < MI; i++)
#pragma unroll
        for (int j = 0; j < NI; j++) wmma::fill_fragment(acc[i][j], 0.f);

    for (int k0 = 0; k0 < K; k0 += BK) {
        // load + convert A tile: fp32 global -> bf16 smem
#pragma unroll
        for (int i = tid; i < BM * (BK / 4); i += NT) {
            int m = i / (BK / 4), kq = (i % (BK / 4)) * 4;
            float4 v = *(const float4*)&A[(long)(m0 + m) * lda + k0 + kq];
            __nv_bfloat162 lo = __floats2bfloat162_rn(v.x, v.y);
            __nv_bfloat162 hi = __floats2bfloat162_rn(v.z, v.w);
            *(__nv_bfloat162*)&As[m][kq]     = lo;
            *(__nv_bfloat162*)&As[m][kq + 2] = hi;
        }
#pragma unroll
        for (int i = tid; i < BK * (BN / 4); i += NT) {
            int kk = i / (BN / 4), nq = (i % (BN / 4)) * 4;
            float4 v = *(const float4*)&B[(long)(k0 + kk) * ldb + n0 + nq];
            __nv_bfloat162 lo = __floats2bfloat162_rn(v.x, v.y);
            __nv_bfloat162 hi = __floats2bfloat162_rn(v.z, v.w);
            *(__nv_bfloat162*)&Bs[kk][nq]     = lo;
            *(__nv_bfloat162*)&Bs[kk][nq + 2] = hi;
        }
        __syncthreads();
#pragma unroll
        for (int k16 = 0; k16 < BK; k16 += 16) {
            wmma::fragment<wmma::matrix_a, 16, 16, 16, __nv_bfloat16, wmma::row_major> af[MI];
            wmma::fragment<wmma::matrix_b, 16, 16, 16, __nv_bfloat16, wmma::row_major> bf[NI];
#pragma unroll
            for (int i = 0; i < MI; i++)
                wmma::load_matrix_sync(af[i], &As[mw0 + i * 16][k16], AP);
#pragma unroll
            for (int j = 0; j < NI; j++)
                wmma::load_matrix_sync(bf[j], &Bs[k16][nw0 + j * 16], BP);
#pragma unroll
            for (int i = 0; i < MI; i++)
#pragma unroll
                for (int j = 0; j < NI; j++)
                    wmma::mma_sync(acc[i][j], af[i], bf[j], acc[i][j]);
        }
        __syncthreads();
    }
#pragma unroll
    for (int i = 0; i < MI; i++)
#pragma unroll
        for (int j = 0; j < NI; j++)
            wmma::store_matrix_sync(&C[(long)(m0 + mw0 + i * 16) * ldc + n0 + nw0 + j * 16],
                                    acc[i][j], ldc, wmma::mem_row_major);
}

// ---------------- gate + routing + gather ----------------
__global__ void gate_route_k(const float* __restrict__ gw_mat, const float* __restrict__ gb) {
    int t = blockIdx.x, tid = threadIdx.x;
    const float* xr = g_h2 + (long)t * D;
    float p[E];
#pragma unroll
    for (int e = 0; e < E; e++) p[e] = 0.f;
    for (int d = tid; d < D; d += 256) {
        float xv = xr[d];
#pragma unroll
        for (int e = 0; e < E; e++) p[e] += xv * gw_mat[d * E + e];
    }
    __shared__ float red[256];
    __shared__ float logits[E];
    for (int e = 0; e < E; e++) {
        red[tid] = p[e]; __syncthreads();
        for (int st = 128; st > 0; st >>= 1) {
            if (tid < st) red[tid] += red[tid + st];
            __syncthreads();
        }
        if (tid == 0) logits[e] = red[0] + gb[e];
        __syncthreads();
    }
    __shared__ int sh_slot, sh_e;
    if (tid == 0) {
        float mx = -3.4e38f;
        for (int e = 0; e < E; e++) mx = fmaxf(mx, logits[e]);
        float Z = 0.f, pr[E];
        for (int e = 0; e < E; e++) { pr[e] = expf(logits[e] - mx); Z += pr[e]; }
        float best = -1.f; int bi = 0;
        for (int e = 0; e < E; e++) {
            float v = pr[e] / Z;
            if (v > best) { best = v; bi = e; }
        }
        int slot = atomicAdd(&g_cnt[bi], 1);
        atomicAdd(&g_sums[bi], best);
        g_tok[bi * T1024 + slot] = t;
        g_gwf[t] = best;
        sh_slot = slot; sh_e = bi;
    }
    __syncthreads();
    float* dst = g_xg + ((long)sh_e * T1024 + sh_slot) * D;
    for (int d = tid; d < D; d += 256) dst[d] = xr[d];
}

// zero-pad gathered rows up to multiple of 128 so full-tile loads are clean
__global__ void pad_k() {
    int e = blockIdx.x;
    int cnt = g_cnt[e];
    int cp = (cnt + 127) & ~127;
    int row = cnt + blockIdx.y;
    if (row >= cp) return;
    float* dst = g_xg + ((long)e * T1024 + row) * D;
    for (int d = threadIdx.x; d < D; d += 256) dst[d] = 0.f;
}

// GLU activation with fused fc bias (exact gelu)
__global__ void moe_act_k(const float* __restrict__ fcb) {
    int e = blockIdx.z;
    int m = blockIdx.y;
    int cp = (g_cnt[e] + 127) & ~127;
    if (m >= cp) return;
    int f = blockIdx.x * 256 + threadIdx.x; // F = 2560, grid.x = 10
    const float* row = g_h12 + ((long)e * T1024 + m) * FC_N;
    const float* b = fcb + (long)e * FC_N;
    float x1 = row[f] + b[f];
    float x2 = row[F + f] + b[F + f];
    float g = 0.5f * x2 * (1.f + erff(x2 * 0.70710678118654752f));
    g_act[((long)e * T1024 + m) * F + f] = x1 * g;
}

// scatter epilogue: out[t] = xres[t] + (y[m] + eout_b) * gw[t]
__global__ void scatter_k(const float* __restrict__ eob, float* __restrict__ out) {
    int e = blockIdx.x, m = blockIdx.y;
    if (m >= g_cnt[e]) return;
    int t = g_tok[e * T1024 + m];
    float g = g_gwf[t];
    const float* y = g_y + ((long)e * T1024 + m) * D;
    const float* bias = eob + (long)e * D;
    for (int d = threadIdx.x; d < D; d += 256)
        out[(long)t * D + d] = g_xres[(long)t * D + d] + (y[d] + bias[d]) * g;
}

__global__ void moe_loss_k(float* __restrict__ out_loss) {
    if (threadIdx.x == 0) {
        float l = 0.f;
        for (int e = 0; e < E; e++) {
            float u = g_sums[e] / ((float)g_cnt[e] + 1e-8f);
            float d = u - 1.f / (float)E;
            l += d * d;
        }
        out_loss[0] = l;
    }
}

// ---------------- host ----------------
static float* sym_addr(const void* sym) {
    void* p = nullptr;
    cudaGetSymbolAddress(&p, sym);
    return (float*)p;
}

extern "C" void kernel_launch(void* const* d_in, const int* in_sizes, int n_in,
                              void* d_out, int out_size) {
    const float* x      = (const float*)d_in[0];
    const int*   ids    = (const int*)d_in[1];
    const float* ln1w   = (const float*)d_in[2];
    const float* ln1b   = (const float*)d_in[3];
    const float* qkvw   = (const float*)d_in[4];
    const float* qkvb   = (const float*)d_in[5];
    const float* aow    = (const float*)d_in[6];
    const float* aob    = (const float*)d_in[7];
    const float* ln2w   = (const float*)d_in[8];
    const float* ln2b   = (const float*)d_in[9];
    const float* gatew  = (const float*)d_in[10];
    const float* gateb  = (const float*)d_in[11];
    const float* fcw    = (const float*)d_in[12];
    const float* fcb    = (const float*)d_in[13];
    const float* eow    = (const float*)d_in[14];
    const float* eob    = (const float*)d_in[15];
    float* out = (float*)d_out;

    float* p_h1   = sym_addr(g_h1);
    float* p_qkv  = sym_addr(g_qkv);
    float* p_KT   = sym_addr(g_KT);
    float* p_S    = sym_addr(g_S);
    float* p_attn = sym_addr(g_attn);
    float* p_tmp  = sym_addr(g_tmp);
    float* p_xres = sym_addr(g_xres);
    float* p_h2   = sym_addr(g_h2);
    float* p_xg   = sym_addr(g_xg);
    float* p_h12  = sym_addr(g_h12);
    float* p_act  = sym_addr(g_act);
    float* p_y    = sym_addr(g_y);
    int*   p_cnt  = (int*)sym_addr(g_cnt);

    zero_k<<<1, 32>>>();
    layernorm_k<<<T1024, 256>>>(x, ln1w, ln1b, p_h1);

    // qkv = h1 @ qkv_w   [1024,1024]x[1024,3072]
    gemm_bf16<128,128,32,64,32><<<dim3(QKVN/128, T1024/128, 1), 256>>>(
        p_h1, D, 0, qkvw, QKVN, 0, p_qkv, QKVN, 0, D, nullptr);
    qkvbias_k<<<T1024, 768>>>(qkvb);
    rope_k<<<dim3(T1024, H), 32>>>();
    ktrans_k<<<(H * HD * T1024) / 256, 256>>>();

    // S[h] = Q[h] @ K[h]^T : [1024,64]x[64,1024] per head
    gemm_bf16<128,128,32,64,32><<<dim3(T1024/128, T1024/128, H), 256>>>(
        p_qkv, QKVN, 64, p_KT, T1024, (long)HD * T1024,
        p_S, T1024, (long)T1024 * T1024, HD, nullptr);

    attn_softmax_k<<<dim3(T1024, H), 256>>>(ids);

    // attn[h] = P[h] @ V[h] : [1024,1024]x[1024,64] per head
    gemm_bf16<128,64,32,64,16><<<dim3(1, T1024/128, H), 256>>>(
        p_S, T1024, (long)T1024 * T1024, p_qkv + 2 * D, QKVN, 64,
        p_attn, D, 64, T1024, nullptr);

    // tmp = attn @ Wo
    gemm_bf16<128,128,32,64,32><<<dim3(D/128, T1024/128, 1), 256>>>(
        p_attn, D, 0, aow, D, 0, p_tmp, D, 0, D, nullptr);

    // xres = x + tmp + bo ; h2 = LN2(xres)
    resln_k<<<T1024, 256>>>(x, p_tmp, aob, ln2w, ln2b, p_xres, p_h2);

    gate_route_k<<<T1024, 256>>>(gatew, gateb);
    pad_k<<<dim3(E, 127), 256>>>();

    // h12 = xg @ fc_w  per expert (guarded by cnt)
    gemm_bf16<128,128,32,64,32><<<dim3(FC_N/128, T1024/128, E), 256>>>(
        p_xg, D, (long)T1024 * D, fcw, FC_N, (long)D * FC_N,
        p_h12, FC_N, (long)T1024 * FC_N, D, p_cnt);

    moe_act_k<<<dim3(F/256, T1024, E), 256>>>(fcb);

    // y = act @ eout_w per expert (guarded)
    gemm_bf16<128,128,32,64,32><<<dim3(D/128, T1024/128, E), 256>>>(
        p_act, F, (long)T1024 * F, eow, D, (long)F * D,
        p_y, D, (long)T1024 * D, F, p_cnt);

    scatter_k<<<dim3(E, T1024), 256>>>(eob, out);

    if (out_size > T1024 * D)
        moe_loss_k<<<1, 32>>>(out + (long)T1024 * D);
}

// round 5
// speedup vs baseline: 3.5029x; 1.1621x over previous
#include <cuda_runtime.h>
#include <cuda_bf16.h>
#include <mma.h>
#include <math.h>
#include <cstdint>
using namespace nvcuda;

// ---------------- constants ----------------
#define T1024 1024
#define D 1024
#define H 16
#define HD 64
#define E 8
#define F 2560
#define QKVN 3072
#define FC_N (2*F)   // 5120

typedef __nv_bfloat16 bf16;

// ---------------- scratch (device globals) ----------------
__device__ float g_qkv[T1024 * QKVN];
__device__ float g_S[(long)H * T1024 * T1024];
__device__ float g_attn[T1024 * D];
__device__ float g_tmp[T1024 * D];
__device__ float g_xres[T1024 * D];
__device__ float g_h2[T1024 * D];
__device__ float g_h12[(long)E * T1024 * FC_N];
__device__ float g_y[(long)E * T1024 * D];
__device__ int   g_cnt[E];
__device__ float g_sums[E];
__device__ int   g_tok[E * T1024];
__device__ float g_gwf[T1024];

__device__ bf16 b_h1[T1024 * D];
__device__ bf16 b_qkv[T1024 * QKVN];
__device__ bf16 b_KT[H * HD * T1024];
__device__ bf16 b_P[(long)H * T1024 * T1024];
__device__ bf16 b_attn[T1024 * D];
__device__ bf16 b_xg[E * T1024 * D];
__device__ bf16 b_act[(long)E * T1024 * F];
__device__ bf16 b_qkvw[D * QKVN];
__device__ bf16 b_aow[D * D];
__device__ bf16 b_fcw[(long)E * D * FC_N];
__device__ bf16 b_eow[(long)E * F * D];

// ---------------- cp.async helpers ----------------
__device__ __forceinline__ void cp16(unsigned int s, const void* g) {
    asm volatile("cp.async.cg.shared.global [%0], [%1], 16;\n" :: "r"(s), "l"(g));
}
__device__ __forceinline__ void cp_commit() {
    asm volatile("cp.async.commit_group;\n");
}
template<int N> __device__ __forceinline__ void cp_wait() {
    asm volatile("cp.async.wait_group %0;\n" :: "n"(N));
}

// ---------------- small kernels ----------------
__global__ void zero_k() {
    int i = threadIdx.x;
    if (i < E) { g_cnt[i] = 0; g_sums[i] = 0.f; }
}

// fp32 -> bf16 convert, 8 elems/thread
__global__ void f2b_k(const float* __restrict__ src, bf16* __restrict__ dst, long n) {
    long i = ((long)blockIdx.x * 256 + threadIdx.x) * 8;
    if (i >= n) return;
    float4 a = *(const float4*)&src[i];
    float4 b = *(const float4*)&src[i + 4];
    __nv_bfloat162 r[4];
    r[0] = __floats2bfloat162_rn(a.x, a.y);
    r[1] = __floats2bfloat162_rn(a.z, a.w);
    r[2] = __floats2bfloat162_rn(b.x, b.y);
    r[3] = __floats2bfloat162_rn(b.z, b.w);
    *(uint4*)&dst[i] = *(uint4*)r;
}

__global__ void layernorm_k(const float* __restrict__ x, const float* __restrict__ w,
                            const float* __restrict__ b, bf16* __restrict__ y) {
    int t = blockIdx.x, tid = threadIdx.x;
    const float* xr = x + (long)t * D;
    float v[4], s = 0.f, ss = 0.f;
#pragma unroll
    for (int i = 0; i < 4; i++) {
        float a = xr[tid + i * 256];
        v[i] = a; s += a; ss += a * a;
    }
    __shared__ float r1[256], r2[256];
    r1[tid] = s; r2[tid] = ss; __syncthreads();
    for (int st = 128; st > 0; st >>= 1) {
        if (tid < st) { r1[tid] += r1[tid + st]; r2[tid] += r2[tid + st]; }
        __syncthreads();
    }
    float mean = r1[0] * (1.f / D);
    float var  = r2[0] * (1.f / D) - mean * mean;
    float inv  = rsqrtf(var + 1e-5f);
#pragma unroll
    for (int i = 0; i < 4; i++) {
        int d = tid + i * 256;
        y[(long)t * D + d] = __float2bfloat16((v[i] - mean) * inv * w[d] + b[d]);
    }
}

// fused: xres = x + tmp + bias ; h2 = LN(xres)  (both fp32)
__global__ void resln_k(const float* __restrict__ x, const float* __restrict__ tmp,
                        const float* __restrict__ bias,
                        const float* __restrict__ w, const float* __restrict__ b,
                        float* __restrict__ xres, float* __restrict__ h2) {
    int t = blockIdx.x, tid = threadIdx.x;
    float v[4], s = 0.f, ss = 0.f;
#pragma unroll
    for (int i = 0; i < 4; i++) {
        int d = tid + i * 256;
        float a = x[(long)t * D + d] + tmp[(long)t * D + d] + bias[d];
        v[i] = a; s += a; ss += a * a;
        xres[(long)t * D + d] = a;
    }
    __shared__ float r1[256], r2[256];
    r1[tid] = s; r2[tid] = ss; __syncthreads();
    for (int st = 128; st > 0; st >>= 1) {
        if (tid < st) { r1[tid] += r1[tid + st]; r2[tid] += r2[tid + st]; }
        __syncthreads();
    }
    float mean = r1[0] * (1.f / D);
    float var  = r2[0] * (1.f / D) - mean * mean;
    float inv  = rsqrtf(var + 1e-5f);
#pragma unroll
    for (int i = 0; i < 4; i++) {
        int d = tid + i * 256;
        h2[(long)t * D + d] = (v[i] - mean) * inv * w[d] + b[d];
    }
}

// fused qkv bias + rope + K-transpose; writes bf16 qkv (+v bias) and KT
__global__ void qkvpost_k(const float* __restrict__ b) {
    int t = blockIdx.x;
    const float* row = g_qkv + (long)t * QKVN;
    bf16* orow = b_qkv + (long)t * QKVN;
    for (int c = threadIdx.x; c < QKVN; c += blockDim.x) {
        float val;
        if (c < 2 * D) {               // q or k, all 64 dims rotated (ROPE==HD)
            int part = c / D;          // 0=q, 1=k
            int within = c - part * D;
            int h = within >> 6, d = within & 63;
            int j = d & 31;
            float inv = powf(10000.f, -(2.f * (float)j) / 64.f);
            float fr = (float)t * inv;
            float cs = cosf(fr), sn = sinf(fr);
            int base = part * D + h * HD;
            float x1 = row[base + j]      + b[base + j];
            float x2 = row[base + j + 32] + b[base + j + 32];
            val = (d < 32) ? (x1 * cs - x2 * sn) : (x1 * sn + x2 * cs);
            if (part == 1)
                b_KT[((long)h * HD + d) * T1024 + t] = __float2bfloat16(val);
        } else {
            val = row[c] + b[c];
        }
        orow[c] = __float2bfloat16(val);
    }
}

__global__ void attn_softmax_k(const int* __restrict__ ids) {
    int q = blockIdx.x, h = blockIdx.y, tid = threadIdx.x;
    const float* row = g_S + ((long)h * T1024 + q) * T1024;
    bf16* prow = b_P + ((long)h * T1024 + q) * T1024;
    int id = ids[q];
    bool glob = (id >= 2 && id < 8);
    float vals[4];
    float mx = -3.4e38f;
#pragma unroll
    for (int i = 0; i < 4; i++) {
        int k = tid + i * 256;
        bool allowed = glob || (q >= k);
        float v = allowed ? row[k] * 0.125f : -3.402823466e38f;
        vals[i] = v;
        mx = fmaxf(mx, v);
    }
    __shared__ float red[256];
    red[tid] = mx; __syncthreads();
    for (int st = 128; st > 0; st >>= 1) {
        if (tid < st) red[tid] = fmaxf(red[tid], red[tid + st]);
        __syncthreads();
    }
    float M = red[0]; __syncthreads();
    float s = 0.f;
#pragma unroll
    for (int i = 0; i < 4; i++) {
        float e = __expf(vals[i] - M);
        vals[i] = e; s += e;
    }
    red[tid] = s; __syncthreads();
    for (int st = 128; st > 0; st >>= 1) {
        if (tid < st) red[tid] += red[tid + st];
        __syncthreads();
    }
    float z = 1.f / red[0];
#pragma unroll
    for (int i = 0; i < 4; i++)
        prow[tid + i * 256] = __float2bfloat16(vals[i] * z);
}

// ---------------- all-bf16 cp.async 3-stage pipelined tensor GEMM ----------------
// C[z] = A[z] @ B[z], fp32 out; M,N multiples of BM/BN; optional per-z row guard.
template<int BM, int BN, int BK, int WM, int WN>
__global__ void __launch_bounds__(256, 2)
gemm_async(const bf16* __restrict__ A, int lda, long sA,
           const bf16* __restrict__ B, int ldb, long sB,
           float* __restrict__ C, int ldc, long sC,
           int K, const int* __restrict__ cntPtr) {
    int z = blockIdx.z;
    int m0 = blockIdx.y * BM;
    if (cntPtr && m0 >= cntPtr[z]) return;
    int n0 = blockIdx.x * BN;
    A += (long)z * sA; B += (long)z * sB; C += (long)z * sC;

    constexpr int S = 3;
    constexpr int AP = BK + 8;
    constexpr int BP = BN + 8;
    __shared__ __align__(16) bf16 As[S][BM][AP];
    __shared__ __align__(16) bf16 Bs[S][BK][BP];

    constexpr int WARPS_M = BM / WM;
    constexpr int WARPS_N = BN / WN;
    constexpr int NT = WARPS_M * WARPS_N * 32;
    constexpr int MI = WM / 16, NI = WN / 16;
    constexpr int ACH = BM * BK / 8;   // 16B chunks in A tile
    constexpr int BCH = BK * BN / 8;

    int tid = threadIdx.x;
    int w = tid >> 5;
    int wm = w % WARPS_M, wn = w / WARPS_M;
    int mw0 = wm * WM, nw0 = wn * WN;

    int nIter = K / BK;

    unsigned int sA0 = (unsigned int)__cvta_generic_to_shared(&As[0][0][0]);
    unsigned int sB0 = (unsigned int)__cvta_generic_to_shared(&Bs[0][0][0]);
    constexpr unsigned int A_STG = BM * AP * 2;
    constexpr unsigned int B_STG = BK * BP * 2;

    auto issue = [&](int stage, int k0) {
#pragma unroll
        for (int c = tid; c < ACH; c += NT) {
            int row = c / (BK / 8);
            int col = (c % (BK / 8)) * 8;
            cp16(sA0 + stage * A_STG + (row * AP + col) * 2,
                 &A[(long)(m0 + row) * lda + k0 + col]);
        }
#pragma unroll
        for (int c = tid; c < BCH; c += NT) {
            int kk = c / (BN / 8);
            int col = (c % (BN / 8)) * 8;
            cp16(sB0 + stage * B_STG + (kk * BP + col) * 2,
                 &B[(long)(k0 + kk) * ldb + n0 + col]);
        }
    };

    // prologue: stages 0..S-2
#pragma unroll
    for (int s = 0; s < S - 1; s++) {
        if (s < nIter) issue(s, s * BK);
        cp_commit();
    }

    wmma::fragment<wmma::accumulator, 16, 16, 16, float> acc[MI][NI];
#pragma unroll
    for (int i = 0; i < MI; i++)
#pragma unroll
        for (int j = 0; j < NI; j++) wmma::fill_fragment(acc[i][j], 0.f);

    for (int it = 0; it < nIter; it++) {
        cp_wait<S - 2>();
        __syncthreads();
        int st = it % S;
#pragma unroll
        for (int k16 = 0; k16 < BK; k16 += 16) {
            wmma::fragment<wmma::matrix_b, 16, 16, 16, bf16, wmma::row_major> bfr[NI];
#pragma unroll
            for (int j = 0; j < NI; j++)
                wmma::load_matrix_sync(bfr[j], &Bs[st][k16][nw0 + j * 16], BP);
#pragma unroll
            for (int i = 0; i < MI; i++) {
                wmma::fragment<wmma::matrix_a, 16, 16, 16, bf16, wmma::row_major> af;
                wmma::load_matrix_sync(af, &As[st][mw0 + i * 16][k16], AP);
#pragma unroll
                for (int j = 0; j < NI; j++)
                    wmma::mma_sync(acc[i][j], af, bfr[j], acc[i][j]);
            }
        }
        int pf = it + S - 1;
        if (pf < nIter) issue(pf % S, pf * BK);
        cp_commit();
    }
#pragma unroll
    for (int i = 0; i < MI; i++)
#pragma unroll
        for (int j = 0; j < NI; j++)
            wmma::store_matrix_sync(&C[(long)(m0 + mw0 + i * 16) * ldc + n0 + nw0 + j * 16],
                                    acc[i][j], ldc, wmma::mem_row_major);
}

// ---------------- gate + routing + gather (bf16 gather) ----------------
__global__ void gate_route_k(const float* __restrict__ gw_mat, const float* __restrict__ gb) {
    int t = blockIdx.x, tid = threadIdx.x;
    const float* xr = g_h2 + (long)t * D;
    float p[E];
#pragma unroll
    for (int e = 0; e < E; e++) p[e] = 0.f;
    for (int d = tid; d < D; d += 256) {
        float xv = xr[d];
#pragma unroll
        for (int e = 0; e < E; e++) p[e] += xv * gw_mat[d * E + e];
    }
    __shared__ float red[256];
    __shared__ float logits[E];
    for (int e = 0; e < E; e++) {
        red[tid] = p[e]; __syncthreads();
        for (int st = 128; st > 0; st >>= 1) {
            if (tid < st) red[tid] += red[tid + st];
            __syncthreads();
        }
        if (tid == 0) logits[e] = red[0] + gb[e];
        __syncthreads();
    }
    __shared__ int sh_slot, sh_e;
    if (tid == 0) {
        float mx = -3.4e38f;
        for (int e = 0; e < E; e++) mx = fmaxf(mx, logits[e]);
        float Z = 0.f, pr[E];
        for (int e = 0; e < E; e++) { pr[e] = expf(logits[e] - mx); Z += pr[e]; }
        float best = -1.f; int bi = 0;
        for (int e = 0; e < E; e++) {
            float v = pr[e] / Z;
            if (v > best) { best = v; bi = e; }
        }
        int slot = atomicAdd(&g_cnt[bi], 1);
        atomicAdd(&g_sums[bi], best);
        g_tok[bi * T1024 + slot] = t;
        g_gwf[t] = best;
        sh_slot = slot; sh_e = bi;
    }
    __syncthreads();
    bf16* dst = b_xg + ((long)sh_e * T1024 + sh_slot) * D;
    for (int d = tid; d < D; d += 256) dst[d] = __float2bfloat16(xr[d]);
}

// GLU activation with fused fc bias (exact gelu) -> bf16
__global__ void moe_act_k(const float* __restrict__ fcb) {
    int e = blockIdx.z;
    int m = blockIdx.y;
    int cp = (g_cnt[e] + 127) & ~127;
    if (m >= cp) return;
    int f = blockIdx.x * 256 + threadIdx.x;
    const float* row = g_h12 + ((long)e * T1024 + m) * FC_N;
    const float* b = fcb + (long)e * FC_N;
    float x1 = row[f] + b[f];
    float x2 = row[F + f] + b[F + f];
    float g = 0.5f * x2 * (1.f + erff(x2 * 0.70710678118654752f));
    b_act[((long)e * T1024 + m) * F + f] = __float2bfloat16(x1 * g);
}

// scatter epilogue: out[t] = xres[t] + (y[m] + eout_b) * gw[t]
__global__ void scatter_k(const float* __restrict__ eob, float* __restrict__ out) {
    int e = blockIdx.x, m = blockIdx.y;
    if (m >= g_cnt[e]) return;
    int t = g_tok[e * T1024 + m];
    float g = g_gwf[t];
    const float* y = g_y + ((long)e * T1024 + m) * D;
    const float* bias = eob + (long)e * D;
    for (int d = threadIdx.x; d < D; d += 256)
        out[(long)t * D + d] = g_xres[(long)t * D + d] + (y[d] + bias[d]) * g;
}

__global__ void moe_loss_k(float* __restrict__ out_loss) {
    if (threadIdx.x == 0) {
        float l = 0.f;
        for (int e = 0; e < E; e++) {
            float u = g_sums[e] / ((float)g_cnt[e] + 1e-8f);
            float d = u - 1.f / (float)E;
            l += d * d;
        }
        out_loss[0] = l;
    }
}

// ---------------- host ----------------
static void* sym_addr(const void* sym) {
    void* p = nullptr;
    cudaGetSymbolAddress(&p, sym);
    return p;
}

extern "C" void kernel_launch(void* const* d_in, const int* in_sizes, int n_in,
                              void* d_out, int out_size) {
    const float* x      = (const float*)d_in[0];
    const int*   ids    = (const int*)d_in[1];
    const float* ln1w   = (const float*)d_in[2];
    const float* ln1b   = (const float*)d_in[3];
    const float* qkvw   = (const float*)d_in[4];
    const float* qkvb   = (const float*)d_in[5];
    const float* aow    = (const float*)d_in[6];
    const float* aob    = (const float*)d_in[7];
    const float* ln2w   = (const float*)d_in[8];
    const float* ln2b   = (const float*)d_in[9];
    const float* gatew  = (const float*)d_in[10];
    const float* gateb  = (const float*)d_in[11];
    const float* fcw    = (const float*)d_in[12];
    const float* fcb    = (const float*)d_in[13];
    const float* eow    = (const float*)d_in[14];
    const float* eob    = (const float*)d_in[15];
    float* out = (float*)d_out;

    float* p_qkv  = (float*)sym_addr(g_qkv);
    float* p_S    = (float*)sym_addr(g_S);
    float* p_attn = (float*)sym_addr(g_attn);
    float* p_tmp  = (float*)sym_addr(g_tmp);
    float* p_xres = (float*)sym_addr(g_xres);
    float* p_h2   = (float*)sym_addr(g_h2);
    float* p_h12  = (float*)sym_addr(g_h12);
    float* p_y    = (float*)sym_addr(g_y);
    int*   p_cnt  = (int*)sym_addr(g_cnt);
    bf16* pb_h1   = (bf16*)sym_addr(b_h1);
    bf16* pb_qkv  = (bf16*)sym_addr(b_qkv);
    bf16* pb_KT   = (bf16*)sym_addr(b_KT);
    bf16* pb_P    = (bf16*)sym_addr(b_P);
    bf16* pb_attn = (bf16*)sym_addr(b_attn);
    bf16* pb_xg   = (bf16*)sym_addr(b_xg);
    bf16* pb_act  = (bf16*)sym_addr(b_act);
    bf16* pb_qkvw = (bf16*)sym_addr(b_qkvw);
    bf16* pb_aow  = (bf16*)sym_addr(b_aow);
    bf16* pb_fcw  = (bf16*)sym_addr(b_fcw);
    bf16* pb_eow  = (bf16*)sym_addr(b_eow);

    zero_k<<<1, 32>>>();

    // weight conversions fp32 -> bf16
    f2b_k<<<(D * QKVN) / (8 * 256), 256>>>(qkvw, pb_qkvw, (long)D * QKVN);
    f2b_k<<<(D * D) / (8 * 256), 256>>>(aow, pb_aow, (long)D * D);
    f2b_k<<<(int)(((long)E * D * FC_N) / (8 * 256)), 256>>>(fcw, pb_fcw, (long)E * D * FC_N);
    f2b_k<<<(int)(((long)E * F * D) / (8 * 256)), 256>>>(eow, pb_eow, (long)E * F * D);

    layernorm_k<<<T1024, 256>>>(x, ln1w, ln1b, pb_h1);

    // qkv = h1 @ qkv_w
    gemm_async<128,128,32,64,32><<<dim3(QKVN/128, T1024/128, 1), 256>>>(
        pb_h1, D, 0, pb_qkvw, QKVN, 0, p_qkv, QKVN, 0, D, nullptr);

    qkvpost_k<<<T1024, 768>>>(qkvb);

    // S[h] = Q[h] @ K[h]^T
    gemm_async<128,128,32,64,32><<<dim3(T1024/128, T1024/128, H), 256>>>(
        pb_qkv, QKVN, 64, pb_KT, T1024, (long)HD * T1024,
        p_S, T1024, (long)T1024 * T1024, HD, nullptr);

    attn_softmax_k<<<dim3(T1024, H), 256>>>(ids);

    // attn[h] = P[h] @ V[h]
    gemm_async<128,64,32,64,16><<<dim3(1, T1024/128, H), 256>>>(
        pb_P, T1024, (long)T1024 * T1024, pb_qkv + 2 * D, QKVN, 64,
        p_attn, D, 64, T1024, nullptr);

    f2b_k<<<(T1024 * D) / (8 * 256), 256>>>(p_attn, pb_attn, (long)T1024 * D);

    // tmp = attn @ Wo
    gemm_async<128,128,32,64,32><<<dim3(D/128, T1024/128, 1), 256>>>(
        pb_attn, D, 0, pb_aow, D, 0, p_tmp, D, 0, D, nullptr);

    resln_k<<<T1024, 256>>>(x, p_tmp, aob, ln2w, ln2b, p_xres, p_h2);

    gate_route_k<<<T1024, 256>>>(gatew, gateb);

    // h12 = xg @ fc_w per expert (guarded)
    gemm_async<128,128,32,64,32><<<dim3(FC_N/128, T1024/128, E), 256>>>(
        pb_xg, D, (long)T1024 * D, pb_fcw, FC_N, (long)D * FC_N,
        p_h12, FC_N, (long)T1024 * FC_N, D, p_cnt);

    moe_act_k<<<dim3(F/256, T1024, E), 256>>>(fcb);

    // y = act @ eout_w per expert (guarded)
    gemm_async<128,128,32,64,32><<<dim3(D/128, T1024/128, E), 256>>>(
        pb_act, F, (long)T1024 * F, pb_eow, D, (long)F * D,
        p_y, D, (long)T1024 * D, F, p_cnt);

    scatter_k<<<dim3(E, T1024), 256>>>(eob, out);

    if (out_size > T1024 * D)
        moe_loss_k<<<1, 32>>>(out + (long)T1024 * D);
}

// round 7
// speedup vs baseline: 3.7438x; 1.0688x over previous
#include <cuda_runtime.h>
#include <cuda_bf16.h>
#include <mma.h>
#include <math.h>
#include <cstdint>
using namespace nvcuda;

// ---------------- constants ----------------
#define T1024 1024
#define D 1024
#define H 16
#define HD 64
#define E 8
#define F 2560
#define QKVN 3072
#define FC_N (2*F)   // 5120

typedef __nv_bfloat16 bf16;

// ---------------- scratch (device globals) ----------------
__device__ float g_qkv[T1024 * QKVN];
__device__ float g_S[(long)H * T1024 * T1024];
__device__ float g_attn[T1024 * D];
__device__ float g_tmp[T1024 * D];
__device__ float g_xres[T1024 * D];
__device__ float g_h2[T1024 * D];
__device__ float g_h12[(long)E * T1024 * FC_N];
__device__ float g_y[(long)E * T1024 * D];
__device__ int   g_cnt[E];
__device__ float g_sums[E];
__device__ int   g_tok[E * T1024];
__device__ float g_gwf[T1024];

__device__ bf16 b_h1[T1024 * D];
__device__ bf16 b_qkv[T1024 * QKVN];
__device__ bf16 b_KT[H * HD * T1024];
__device__ bf16 b_P[(long)H * T1024 * T1024];
__device__ bf16 b_attn[T1024 * D];
__device__ bf16 b_xg[E * T1024 * D];
__device__ bf16 b_act[(long)E * T1024 * F];
__device__ bf16 b_qkvw[D * QKVN];
__device__ bf16 b_aow[D * D];
__device__ bf16 b_fcw[(long)E * D * FC_N];
__device__ bf16 b_eow[(long)E * F * D];

// ---------------- cp.async helpers ----------------
__device__ __forceinline__ void cp16(unsigned int s, const void* g) {
    asm volatile("cp.async.cg.shared.global [%0], [%1], 16;\n" :: "r"(s), "l"(g));
}
__device__ __forceinline__ void cp_commit() {
    asm volatile("cp.async.commit_group;\n");
}
template<int N> __device__ __forceinline__ void cp_wait() {
    asm volatile("cp.async.wait_group %0;\n" :: "n"(N));
}

// ---------------- small kernels ----------------
__global__ void zero_k() {
    int i = threadIdx.x;
    if (i < E) { g_cnt[i] = 0; g_sums[i] = 0.f; }
}

// fp32 -> bf16 convert, 8 elems/thread
__global__ void f2b_k(const float* __restrict__ src, bf16* __restrict__ dst, long n) {
    long i = ((long)blockIdx.x * 256 + threadIdx.x) * 8;
    if (i >= n) return;
    float4 a = *(const float4*)&src[i];
    float4 b = *(const float4*)&src[i + 4];
    __nv_bfloat162 r[4];
    r[0] = __floats2bfloat162_rn(a.x, a.y);
    r[1] = __floats2bfloat162_rn(a.z, a.w);
    r[2] = __floats2bfloat162_rn(b.x, b.y);
    r[3] = __floats2bfloat162_rn(b.z, b.w);
    *(uint4*)&dst[i] = *(uint4*)r;
}

__global__ void layernorm_k(const float* __restrict__ x, const float* __restrict__ w,
                            const float* __restrict__ b, bf16* __restrict__ y) {
    int t = blockIdx.x, tid = threadIdx.x;
    const float* xr = x + (long)t * D;
    float v[4], s = 0.f, ss = 0.f;
#pragma unroll
    for (int i = 0; i < 4; i++) {
        float a = xr[tid + i * 256];
        v[i] = a; s += a; ss += a * a;
    }
    __shared__ float r1[256], r2[256];
    r1[tid] = s; r2[tid] = ss; __syncthreads();
    for (int st = 128; st > 0; st >>= 1) {
        if (tid < st) { r1[tid] += r1[tid + st]; r2[tid] += r2[tid + st]; }
        __syncthreads();
    }
    float mean = r1[0] * (1.f / D);
    float var  = r2[0] * (1.f / D) - mean * mean;
    float inv  = rsqrtf(var + 1e-5f);
#pragma unroll
    for (int i = 0; i < 4; i++) {
        int d = tid + i * 256;
        y[(long)t * D + d] = __float2bfloat16((v[i] - mean) * inv * w[d] + b[d]);
    }
}

// fused: xres = x + tmp + bias ; h2 = LN(xres)  (both fp32)
__global__ void resln_k(const float* __restrict__ x, const float* __restrict__ tmp,
                        const float* __restrict__ bias,
                        const float* __restrict__ w, const float* __restrict__ b,
                        float* __restrict__ xres, float* __restrict__ h2) {
    int t = blockIdx.x, tid = threadIdx.x;
    float v[4], s = 0.f, ss = 0.f;
#pragma unroll
    for (int i = 0; i < 4; i++) {
        int d = tid + i * 256;
        float a = x[(long)t * D + d] + tmp[(long)t * D + d] + bias[d];
        v[i] = a; s += a; ss += a * a;
        xres[(long)t * D + d] = a;
    }
    __shared__ float r1[256], r2[256];
    r1[tid] = s; r2[tid] = ss; __syncthreads();
    for (int st = 128; st > 0; st >>= 1) {
        if (tid < st) { r1[tid] += r1[tid + st]; r2[tid] += r2[tid + st]; }
        __syncthreads();
    }
    float mean = r1[0] * (1.f / D);
    float var  = r2[0] * (1.f / D) - mean * mean;
    float inv  = rsqrtf(var + 1e-5f);
#pragma unroll
    for (int i = 0; i < 4; i++) {
        int d = tid + i * 256;
        h2[(long)t * D + d] = (v[i] - mean) * inv * w[d] + b[d];
    }
}

// fused qkv bias + rope + K-transpose; writes bf16 qkv (+v bias) and KT
__global__ void qkvpost_k(const float* __restrict__ b) {
    int t = blockIdx.x;
    const float* row = g_qkv + (long)t * QKVN;
    bf16* orow = b_qkv + (long)t * QKVN;
    for (int c = threadIdx.x; c < QKVN; c += blockDim.x) {
        float val;
        if (c < 2 * D) {               // q or k, all 64 dims rotated (ROPE==HD)
            int part = c / D;          // 0=q, 1=k
            int within = c - part * D;
            int h = within >> 6, d = within & 63;
            int j = d & 31;
            float inv = powf(10000.f, -(2.f * (float)j) / 64.f);
            float fr = (float)t * inv;
            float cs = cosf(fr), sn = sinf(fr);
            int base = part * D + h * HD;
            float x1 = row[base + j]      + b[base + j];
            float x2 = row[base + j + 32] + b[base + j + 32];
            val = (d < 32) ? (x1 * cs - x2 * sn) : (x1 * sn + x2 * cs);
            if (part == 1)
                b_KT[((long)h * HD + d) * T1024 + t] = __float2bfloat16(val);
        } else {
            val = row[c] + b[c];
        }
        orow[c] = __float2bfloat16(val);
    }
}

__global__ void attn_softmax_k(const int* __restrict__ ids) {
    int q = blockIdx.x, h = blockIdx.y, tid = threadIdx.x;
    const float* row = g_S + ((long)h * T1024 + q) * T1024;
    bf16* prow = b_P + ((long)h * T1024 + q) * T1024;
    int id = ids[q];
    bool glob = (id >= 2 && id < 8);
    float vals[4];
    float mx = -3.4e38f;
#pragma unroll
    for (int i = 0; i < 4; i++) {
        int k = tid + i * 256;
        bool allowed = glob || (q >= k);
        float v = allowed ? row[k] * 0.125f : -3.402823466e38f;
        vals[i] = v;
        mx = fmaxf(mx, v);
    }
    __shared__ float red[256];
    red[tid] = mx; __syncthreads();
    for (int st = 128; st > 0; st >>= 1) {
        if (tid < st) red[tid] = fmaxf(red[tid], red[tid + st]);
        __syncthreads();
    }
    float M = red[0]; __syncthreads();
    float s = 0.f;
#pragma unroll
    for (int i = 0; i < 4; i++) {
        float e = __expf(vals[i] - M);
        vals[i] = e; s += e;
    }
    red[tid] = s; __syncthreads();
    for (int st = 128; st > 0; st >>= 1) {
        if (tid < st) red[tid] += red[tid + st];
        __syncthreads();
    }
    float z = 1.f / red[0];
#pragma unroll
    for (int i = 0; i < 4; i++)
        prow[tid + i * 256] = __float2bfloat16(vals[i] * z);
}

// ---------------- all-bf16 cp.async 3-stage pipelined tensor GEMM ----------------
// C[z] = A[z] @ B[z], fp32 out; M,N multiples of BM/BN; optional per-z row guard.
// Warp tile WM x WN; threads = (BM/WM)*(BN/WN)*32.
template<int BM, int BN, int BK, int WM, int WN>
__global__ void __launch_bounds__((BM / WM) * (BN / WN) * 32, 2)
gemm_async(const bf16* __restrict__ A, int lda, long sA,
           const bf16* __restrict__ B, int ldb, long sB,
           float* __restrict__ C, int ldc, long sC,
           int K, const int* __restrict__ cntPtr) {
    int z = blockIdx.z;
    int m0 = blockIdx.y * BM;
    if (cntPtr && m0 >= cntPtr[z]) return;
    int n0 = blockIdx.x * BN;
    A += (long)z * sA; B += (long)z * sB; C += (long)z * sC;

    constexpr int S = 3;
    constexpr int AP = BK + 8;
    constexpr int BP = BN + 8;
    __shared__ __align__(16) bf16 As[S][BM][AP];
    __shared__ __align__(16) bf16 Bs[S][BK][BP];

    constexpr int WARPS_M = BM / WM;
    constexpr int WARPS_N = BN / WN;
    constexpr int NT = WARPS_M * WARPS_N * 32;
    constexpr int MI = WM / 16, NI = WN / 16;
    constexpr int ACH = BM * BK / 8;   // 16B chunks in A tile
    constexpr int BCH = BK * BN / 8;

    int tid = threadIdx.x;
    int w = tid >> 5;
    int wm = w % WARPS_M, wn = w / WARPS_M;
    int mw0 = wm * WM, nw0 = wn * WN;

    int nIter = K / BK;

    unsigned int sA0 = (unsigned int)__cvta_generic_to_shared(&As[0][0][0]);
    unsigned int sB0 = (unsigned int)__cvta_generic_to_shared(&Bs[0][0][0]);
    constexpr unsigned int A_STG = BM * AP * 2;
    constexpr unsigned int B_STG = BK * BP * 2;

    auto issue = [&](int stage, int k0) {
#pragma unroll
        for (int c = tid; c < ACH; c += NT) {
            int row = c / (BK / 8);
            int col = (c % (BK / 8)) * 8;
            cp16(sA0 + stage * A_STG + (row * AP + col) * 2,
                 &A[(long)(m0 + row) * lda + k0 + col]);
        }
#pragma unroll
        for (int c = tid; c < BCH; c += NT) {
            int kk = c / (BN / 8);
            int col = (c % (BN / 8)) * 8;
            cp16(sB0 + stage * B_STG + (kk * BP + col) * 2,
                 &B[(long)(k0 + kk) * ldb + n0 + col]);
        }
    };

    // prologue: stages 0..S-2
#pragma unroll
    for (int s = 0; s < S - 1; s++) {
        if (s < nIter) issue(s, s * BK);
        cp_commit();
    }

    wmma::fragment<wmma::accumulator, 16, 16, 16, float> acc[MI][NI];
#pragma unroll
    for (int i = 0; i < MI; i++)
#pragma unroll
        for (int j = 0; j < NI; j++) wmma::fill_fragment(acc[i][j], 0.f);

    for (int it = 0; it < nIter; it++) {
        cp_wait<S - 2>();
        __syncthreads();
        int st = it % S;
#pragma unroll
        for (int k16 = 0; k16 < BK; k16 += 16) {
            wmma::fragment<wmma::matrix_b, 16, 16, 16, bf16, wmma::row_major> bfr[NI];
#pragma unroll
            for (int j = 0; j < NI; j++)
                wmma::load_matrix_sync(bfr[j], &Bs[st][k16][nw0 + j * 16], BP);
#pragma unroll
            for (int i = 0; i < MI; i++) {
                wmma::fragment<wmma::matrix_a, 16, 16, 16, bf16, wmma::row_major> af;
                wmma::load_matrix_sync(af, &As[st][mw0 + i * 16][k16], AP);
#pragma unroll
                for (int j = 0; j < NI; j++)
                    wmma::mma_sync(acc[i][j], af, bfr[j], acc[i][j]);
            }
        }
        int pf = it + S - 1;
        if (pf < nIter) issue(pf % S, pf * BK);
        cp_commit();
    }
#pragma unroll
    for (int i = 0; i < MI; i++)
#pragma unroll
        for (int j = 0; j < NI; j++)
            wmma::store_matrix_sync(&C[(long)(m0 + mw0 + i * 16) * ldc + n0 + nw0 + j * 16],
                                    acc[i][j], ldc, wmma::mem_row_major);
}

// ---------------- gate + routing + gather (bf16 gather) ----------------
__global__ void gate_route_k(const float* __restrict__ gw_mat, const float* __restrict__ gb) {
    int t = blockIdx.x, tid = threadIdx.x;
    const float* xr = g_h2 + (long)t * D;
    float p[E];
#pragma unroll
    for (int e = 0; e < E; e++) p[e] = 0.f;
    for (int d = tid; d < D; d += 256) {
        float xv = xr[d];
#pragma unroll
        for (int e = 0; e < E; e++) p[e] += xv * gw_mat[d * E + e];
    }
    __shared__ float red[256];
    __shared__ float logits[E];
    for (int e = 0; e < E; e++) {
        red[tid] = p[e]; __syncthreads();
        for (int st = 128; st > 0; st >>= 1) {
            if (tid < st) red[tid] += red[tid + st];
            __syncthreads();
        }
        if (tid == 0) logits[e] = red[0] + gb[e];
        __syncthreads();
    }
    __shared__ int sh_slot, sh_e;
    if (tid == 0) {
        float mx = -3.4e38f;
        for (int e = 0; e < E; e++) mx = fmaxf(mx, logits[e]);
        float Z = 0.f, pr[E];
        for (int e = 0; e < E; e++) { pr[e] = expf(logits[e] - mx); Z += pr[e]; }
        float best = -1.f; int bi = 0;
        for (int e = 0; e < E; e++) {
            float v = pr[e] / Z;
            if (v > best) { best = v; bi = e; }
        }
        int slot = atomicAdd(&g_cnt[bi], 1);
        atomicAdd(&g_sums[bi], best);
        g_tok[bi * T1024 + slot] = t;
        g_gwf[t] = best;
        sh_slot = slot; sh_e = bi;
    }
    __syncthreads();
    bf16* dst = b_xg + ((long)sh_e * T1024 + sh_slot) * D;
    for (int d = tid; d < D; d += 256) dst[d] = __float2bfloat16(xr[d]);
}

// GLU activation with fused fc bias (exact gelu) -> bf16
__global__ void moe_act_k(const float* __restrict__ fcb) {
    int e = blockIdx.z;
    int m = blockIdx.y;
    int cp = (g_cnt[e] + 127) & ~127;
    if (m >= cp) return;
    int f = blockIdx.x * 256 + threadIdx.x;
    const float* row = g_h12 + ((long)e * T1024 + m) * FC_N;
    const float* b = fcb + (long)e * FC_N;
    float x1 = row[f] + b[f];
    float x2 = row[F + f] + b[F + f];
    float g = 0.5f * x2 * (1.f + erff(x2 * 0.70710678118654752f));
    b_act[((long)e * T1024 + m) * F + f] = __float2bfloat16(x1 * g);
}

// scatter epilogue: out[t] = xres[t] + (y[m] + eout_b) * gw[t]
__global__ void scatter_k(const float* __restrict__ eob, float* __restrict__ out) {
    int e = blockIdx.x, m = blockIdx.y;
    if (m >= g_cnt[e]) return;
    int t = g_tok[e * T1024 + m];
    float g = g_gwf[t];
    const float* y = g_y + ((long)e * T1024 + m) * D;
    const float* bias = eob + (long)e * D;
    for (int d = threadIdx.x; d < D; d += 256)
        out[(long)t * D + d] = g_xres[(long)t * D + d] + (y[d] + bias[d]) * g;
}

__global__ void moe_loss_k(float* __restrict__ out_loss) {
    if (threadIdx.x == 0) {
        float l = 0.f;
        for (int e = 0; e < E; e++) {
            float u = g_sums[e] / ((float)g_cnt[e] + 1e-8f);
            float d = u - 1.f / (float)E;
            l += d * d;
        }
        out_loss[0] = l;
    }
}

// ---------------- host ----------------
static void* sym_addr(const void* sym) {
    void* p = nullptr;
    cudaGetSymbolAddress(&p, sym);
    return p;
}

extern "C" void kernel_launch(void* const* d_in, const int* in_sizes, int n_in,
                              void* d_out, int out_size) {
    const float* x      = (const float*)d_in[0];
    const int*   ids    = (const int*)d_in[1];
    const float* ln1w   = (const float*)d_in[2];
    const float* ln1b   = (const float*)d_in[3];
    const float* qkvw   = (const float*)d_in[4];
    const float* qkvb   = (const float*)d_in[5];
    const float* aow    = (const float*)d_in[6];
    const float* aob    = (const float*)d_in[7];
    const float* ln2w   = (const float*)d_in[8];
    const float* ln2b   = (const float*)d_in[9];
    const float* gatew  = (const float*)d_in[10];
    const float* gateb  = (const float*)d_in[11];
    const float* fcw    = (const float*)d_in[12];
    const float* fcb    = (const float*)d_in[13];
    const float* eow    = (const float*)d_in[14];
    const float* eob    = (const float*)d_in[15];
    float* out = (float*)d_out;

    float* p_qkv  = (float*)sym_addr(g_qkv);
    float* p_S    = (float*)sym_addr(g_S);
    float* p_attn = (float*)sym_addr(g_attn);
    float* p_tmp  = (float*)sym_addr(g_tmp);
    float* p_xres = (float*)sym_addr(g_xres);
    float* p_h2   = (float*)sym_addr(g_h2);
    float* p_h12  = (float*)sym_addr(g_h12);
    float* p_y    = (float*)sym_addr(g_y);
    int*   p_cnt  = (int*)sym_addr(g_cnt);
    bf16* pb_h1   = (bf16*)sym_addr(b_h1);
    bf16* pb_qkv  = (bf16*)sym_addr(b_qkv);
    bf16* pb_KT   = (bf16*)sym_addr(b_KT);
    bf16* pb_P    = (bf16*)sym_addr(b_P);
    bf16* pb_attn = (bf16*)sym_addr(b_attn);
    bf16* pb_xg   = (bf16*)sym_addr(b_xg);
    bf16* pb_act  = (bf16*)sym_addr(b_act);
    bf16* pb_qkvw = (bf16*)sym_addr(b_qkvw);
    bf16* pb_aow  = (bf16*)sym_addr(b_aow);
    bf16* pb_fcw  = (bf16*)sym_addr(b_fcw);
    bf16* pb_eow  = (bf16*)sym_addr(b_eow);

    zero_k<<<1, 32>>>();

    // weight conversions fp32 -> bf16
    f2b_k<<<(D * QKVN) / (8 * 256), 256>>>(qkvw, pb_qkvw, (long)D * QKVN);
    f2b_k<<<(D * D) / (8 * 256), 256>>>(aow, pb_aow, (long)D * D);
    f2b_k<<<(int)(((long)E * D * FC_N) / (8 * 256)), 256>>>(fcw, pb_fcw, (long)E * D * FC_N);
    f2b_k<<<(int)(((long)E * F * D) / (8 * 256)), 256>>>(eow, pb_eow, (long)E * F * D);

    layernorm_k<<<T1024, 256>>>(x, ln1w, ln1b, pb_h1);

    // qkv = h1 @ qkv_w
    gemm_async<128,128,32,64,64><<<dim3(QKVN/128, T1024/128, 1), 128>>>(
        pb_h1, D, 0, pb_qkvw, QKVN, 0, p_qkv, QKVN, 0, D, nullptr);

    qkvpost_k<<<T1024, 768>>>(qkvb);

    // S[h] = Q[h] @ K[h]^T
    gemm_async<128,128,32,64,64><<<dim3(T1024/128, T1024/128, H), 128>>>(
        pb_qkv, QKVN, 64, pb_KT, T1024, (long)HD * T1024,
        p_S, T1024, (long)T1024 * T1024, HD, nullptr);

    attn_softmax_k<<<dim3(T1024, H), 256>>>(ids);

    // attn[h] = P[h] @ V[h]
    gemm_async<128,64,32,64,32><<<dim3(1, T1024/128, H), 128>>>(
        pb_P, T1024, (long)T1024 * T1024, pb_qkv + 2 * D, QKVN, 64,
        p_attn, D, 64, T1024, nullptr);

    f2b_k<<<(T1024 * D) / (8 * 256), 256>>>(p_attn, pb_attn, (long)T1024 * D);

    // tmp = attn @ Wo
    gemm_async<128,128,32,64,64><<<dim3(D/128, T1024/128, 1), 128>>>(
        pb_attn, D, 0, pb_aow, D, 0, p_tmp, D, 0, D, nullptr);

    resln_k<<<T1024, 256>>>(x, p_tmp, aob, ln2w, ln2b, p_xres, p_h2);

    gate_route_k<<<T1024, 256>>>(gatew, gateb);

    // h12 = xg @ fc_w per expert (guarded)
    gemm_async<128,128,32,64,64><<<dim3(FC_N/128, T1024/128, E), 128>>>(
        pb_xg, D, (long)T1024 * D, pb_fcw, FC_N, (long)D * FC_N,
        p_h12, FC_N, (long)T1024 * FC_N, D, p_cnt);

    moe_act_k<<<dim3(F/256, T1024, E), 256>>>(fcb);

    // y = act @ eout_w per expert (guarded)
    gemm_async<128,128,32,64,64><<<dim3(D/128, T1024/128, E), 128>>>(
        pb_act, F, (long)T1024 * F, pb_eow, D, (long)F * D,
        p_y, D, (long)T1024 * D, F, p_cnt);

    scatter_k<<<dim3(E, T1024), 256>>>(eob, out);

    if (out_size > T1024 * D)
        moe_loss_k<<<1, 32>>>(out + (long)T1024 * D);
}